// round 8
// baseline (speedup 1.0000x reference)
#include <cuda_runtime.h>

#define NT 256
#define NBLK 8192                  // 8192 blocks x 1024-idx chunks = 2^23
#define SPATIAL (256 * 256 * 64)   // 4194304
#define XS (256 * 64)              // x stride
#define YS 64                      // y stride

__device__ float g_pb[NBLK];
__device__ float g_pp[NBLK];
__device__ float g_pd[NBLK];
__device__ unsigned int g_cnt = 0;

__global__ __launch_bounds__(NT, 6) void loss_kernel(
    const float* __restrict__ outp, const float* __restrict__ tgt,
    float* __restrict__ out)
{
    const float EPS = 1e-10f;
    const float C8  = 0.0125f;        // 0.125 * DX
    const float C6  = 0.1f / 6.0f;    // DX/6
    const float CZ  = 0.0025f;        // 0.25 * DX * DY

    const int tid  = threadIdx.x;
    // chunk = 1024 consecutive idx = 16 y-rows x 64 z, fixed (b, x)
    const int base = blockIdx.x << 10;
    const int b    = base >> 22;
    const int rem  = base & (SPATIAL - 1);
    const int x    = rem >> 14;            // constant per block
    const int y0   = (rem >> 6) & 255;     // chunk starting y (multiple of 16)
    const int z    = tid & 63;             // constant per thread
    const int dy   = tid >> 6;             // 0..3

    const bool xz_ok = (x < 255) & (z < 63);

    const float* po0 = outp + (size_t)b * 3 * SPATIAL + x * XS + (y0 + dy) * YS + z;
    const float* pt0 = tgt  + (size_t)b * 4 * SPATIAL + x * XS + (y0 + dy) * YS + z;

    float sb = 0.f, sp = 0.f, sd = 0.f;

    for (int it = 0; it < 4; ++it) {
        const float* po = po0 + it * 4 * YS;   // bx_p at (b,x,y,z)
        const float* pt = pt0 + it * 4 * YS;   // bx_t
        const int y = y0 + it * 4 + dy;

        // ---- pointwise losses ----
        {
            const float bxp = po[0], byp = po[SPATIAL], bzp = po[2 * SPATIAL];
            const float bxt = pt[0], byt = pt[SPATIAL], bzt = pt[2 * SPATIAL];
            const float bxt2 = bxt * bxt, byt2 = byt * byt, bzt2 = bzt * bzt;
            const float t1 = bxp * bxp + byp * byp - bxt2 - byt2;
            sb += t1 * t1 / (bxt2 + byt2 + EPS);
            const float dv = bzp - bzt;
            const float dv2 = dv * dv;
            sb += dv2 * dv2 / (bzt2 + EPS);
            const float cr = bxp * byt - byp * bxt;
            sp += cr * cr / (bxt2 + byt2 + bzt2 + EPS);
        }

        // ---- divergence flux loss, coefficient-streamed ----
        if (xz_ok && y < 255) {
            // corner c = (i,j,k) -> offset i*XS + j*YS + k
            const float* pz = pt + 3 * SPATIAL;
            const float z0 = pz[0],       z1 = pz[1];
            const float z2 = pz[YS],      z3 = pz[YS + 1];
            const float z4 = pz[XS],      z5 = pz[XS + 1];
            const float z6 = pz[XS + YS], z7 = pz[XS + YS + 1];

            // bx coefficients
            const float q1 =  C8 * (z5 - z4 + z7 - z6);
            const float q2 = -C8 * (z1 - z0 + z3 - z2);
            const float r1 =  C6 * (z1 - z5);
            const float r2 =  C6 * (z3 - z7);
            const float r3 =  C6 * (z4 - z0);
            const float r4 =  C6 * (z6 - z2);
            // by coefficients
            const float s1 =  C8 * (z3 - z2 + z7 - z6);
            const float s2 = -C8 * (z1 - z0 + z5 - z4);
            const float u1 =  C6 * (z5 - z7);
            const float u2 =  C6 * (z1 - z3);
            const float u3 =  C6 * (z6 - z4);
            const float u4 =  C6 * (z2 - z0);

            float num, bxc, byc, bzc;
            {   // bx batch
                const float c0 = po[0],       c1 = po[1];
                const float c2 = po[YS],      c3 = po[YS + 1];
                const float c4 = po[XS],      c5 = po[XS + 1];
                const float c6 = po[XS + YS], c7 = po[XS + YS + 1];
                num = c0 * (q2 + r3) + c1 * (q2 + r1)
                    + c2 * (q2 + r4) + c3 * (q2 + r2)
                    + (c4 + c6) * (q1 + (r3 + r4))
                    + (c5 + c7) * (q1 + (r1 + r2));
                bxc = ((c0 + c1) + (c2 + c3)) + ((c4 + c5) + (c6 + c7));
            }
            {   // by batch
                const float* py = po + SPATIAL;
                const float c0 = py[0],       c1 = py[1];
                const float c2 = py[YS],      c3 = py[YS + 1];
                const float c4 = py[XS],      c5 = py[XS + 1];
                const float c6 = py[XS + YS], c7 = py[XS + YS + 1];
                num += c0 * (s2 + u4) + c1 * (s2 + u2)
                     + c4 * (s2 + u3) + c5 * (s2 + u1)
                     + (c2 + c6) * (s1 + (u3 + u4))
                     + (c3 + c7) * (s1 + (u1 + u2));
                byc = ((c0 + c1) + (c2 + c3)) + ((c4 + c5) + (c6 + c7));
            }
            {   // bz batch
                const float* pb = po + 2 * SPATIAL;
                const float c0 = pb[0],       c1 = pb[1];
                const float c2 = pb[YS],      c3 = pb[YS + 1];
                const float c4 = pb[XS],      c5 = pb[XS + 1];
                const float c6 = pb[XS + YS], c7 = pb[XS + YS + 1];
                num += CZ * (((c1 + c3) + (c5 + c7)) - ((c0 + c2) + (c4 + c6)));
                bzc = ((c0 + c1) + (c2 + c3)) + ((c4 + c5) + (c6 + c7));
            }
            bxc *= 0.125f; byc *= 0.125f; bzc *= 0.125f;
            const float den = bxc * bxc + byc * byc + bzc * bzc + EPS;
            sd += num * num / den;
        }
    }

    // ---- deterministic block reduction ----
    __shared__ float shb[NT], shp[NT], shd[NT];
    shb[tid] = sb;
    shp[tid] = sp;
    shd[tid] = sd;
    __syncthreads();
    for (int s = NT / 2; s > 0; s >>= 1) {
        if (tid < s) {
            shb[tid] += shb[tid + s];
            shp[tid] += shp[tid + s];
            shd[tid] += shd[tid + s];
        }
        __syncthreads();
    }

    __shared__ bool isLast;
    if (tid == 0) {
        g_pb[blockIdx.x] = shb[0];
        g_pp[blockIdx.x] = shp[0];
        g_pd[blockIdx.x] = shd[0];
        __threadfence();
        isLast = (atomicAdd(&g_cnt, 1u) == NBLK - 1);
    }
    __syncthreads();

    // ---- last block: final deterministic reduce in double ----
    if (isLast) {
        __threadfence();
        __shared__ double rb[NT], rp[NT], rd[NT];
        double db = 0.0, dp = 0.0, dd = 0.0;
        for (int i = tid; i < NBLK; i += NT) {
            db += (double)__ldcg(&g_pb[i]);
            dp += (double)__ldcg(&g_pp[i]);
            dd += (double)__ldcg(&g_pd[i]);
        }
        rb[tid] = db; rp[tid] = dp; rd[tid] = dd;
        __syncthreads();
        for (int s = NT / 2; s > 0; s >>= 1) {
            if (tid < s) {
                rb[tid] += rb[tid + s];
                rp[tid] += rp[tid + s];
                rd[tid] += rd[tid + s];
            }
            __syncthreads();
        }
        if (tid == 0) {
            const double N = 8388608.0;            // 2*256*256*64
            const double M = 8193150.0;            // 2*255*255*63
            const double loss_b   = rb[0] / N;
            const double loss_p   = rp[0] / N;
            const double loss_div = rd[0] / M * 1.0e4;   // / DX^2 / DY^2
            out[0] = (float)(1000.0 * loss_b + 1000.0 * loss_p);
            out[1] = (float)(100.0 * loss_div);
            g_cnt = 0;                              // reset for graph replay
        }
    }
}

extern "C" void kernel_launch(void* const* d_in, const int* in_sizes, int n_in,
                              void* d_out, int out_size)
{
    const float* outputs = (const float*)d_in[0];
    const float* targets = (const float*)d_in[1];
    float* out = (float*)d_out;
    loss_kernel<<<NBLK, NT>>>(outputs, targets, out);
}

// round 10
// speedup vs baseline: 1.0134x; 1.0134x over previous
#include <cuda_runtime.h>

#define NT 256
#define NB 2048
#define SPATIAL (256 * 256 * 64)   // 4194304
#define NV (1 << 22)               // work items; each covers 2 z-adjacent cells
#define XS (256 * 64)              // x stride
#define YS 64                      // y stride

__device__ float g_pb[NB];
__device__ float g_pp[NB];
__device__ float g_pd[NB];
__device__ unsigned int g_cnt = 0;

__global__ __launch_bounds__(NT, 5) void loss_kernel(
    const float* __restrict__ outp, const float* __restrict__ tgt,
    float* __restrict__ out)
{
    const float EPS = 1e-10f;
    const float C8  = 0.0125f;        // 0.125 * DX
    const float C6  = 0.1f / 6.0f;    // DX/6
    const float CZ  = 0.0025f;        // 0.25 * DX * DY

    float sb = 0.f, sp = 0.f, sd = 0.f;

    // v bits: z2[0:5) y[5:13) x[13:21) b[21]
    for (int v = blockIdx.x * NT + threadIdx.x; v < NV; v += NB * NT) {
        const int b  = v >> 21;
        const int s  = v & ((1 << 21) - 1);
        const int z2 = s & 31;
        const int y  = (s >> 5) & 255;
        const int x  = s >> 13;
        const int off = ((s >> 5) << 6) + (z2 << 1);   // x*XS + y*YS + 2*z2

        const float* po = outp + (size_t)b * 3 * SPATIAL + off;  // bx_p
        const float* pt = tgt  + (size_t)b * 4 * SPATIAL + off;  // bx_t

        // ---- pointwise losses, both cells via float2 ----
        {
            const float2 vbxp = *(const float2*)(po);
            const float2 vbyp = *(const float2*)(po + SPATIAL);
            const float2 vbzp = *(const float2*)(po + 2 * SPATIAL);
            const float2 vbxt = *(const float2*)(pt);
            const float2 vbyt = *(const float2*)(pt + SPATIAL);
            const float2 vbzt = *(const float2*)(pt + 2 * SPATIAL);
            #pragma unroll
            for (int k = 0; k < 2; k++) {
                const float bxp = k ? vbxp.y : vbxp.x;
                const float byp = k ? vbyp.y : vbyp.x;
                const float bzp = k ? vbzp.y : vbzp.x;
                const float bxt = k ? vbxt.y : vbxt.x;
                const float byt = k ? vbyt.y : vbyt.x;
                const float bzt = k ? vbzt.y : vbzt.x;
                const float bxt2 = bxt * bxt, byt2 = byt * byt, bzt2 = bzt * bzt;
                const float t1 = bxp * bxp + byp * byp - bxt2 - byt2;
                sb += t1 * t1 / (bxt2 + byt2 + EPS);
                const float dv = bzp - bzt;
                const float dv2 = dv * dv;
                sb += dv2 * dv2 / (bzt2 + EPS);
                const float cr = bxp * byt - byp * bxt;
                sp += cr * cr / (bxt2 + byt2 + bzt2 + EPS);
            }
        }

        // ---- divergence flux, 2 cells sharing the z+1 plane ----
        if (x < 255 && y < 255) {
            const bool tail = (z2 < 31);     // cell1 (z odd) valid; z+2 exists
            const float* pz = pt + 3 * SPATIAL;

            // z-field window: rows r: 0=(0,0) 1=(0,1) 2=(1,0) 3=(1,1)
            const float2 t0 = *(const float2*)(pz);
            const float2 t1 = *(const float2*)(pz + YS);
            const float2 t2 = *(const float2*)(pz + XS);
            const float2 t3 = *(const float2*)(pz + XS + YS);
            const float e0 = tail ? pz[2] : 0.f;
            const float e1 = tail ? pz[YS + 2] : 0.f;
            const float e2 = tail ? pz[XS + 2] : 0.f;
            const float e3 = tail ? pz[XS + YS + 2] : 0.f;

            float num0 = 0.f, num1 = 0.f;
            float cx0, cx1, cy0, cy1, cz0, cz1;

            {   // bx batch
                const float2 f0 = *(const float2*)(po);
                const float2 f1 = *(const float2*)(po + YS);
                const float2 f2 = *(const float2*)(po + XS);
                const float2 f3 = *(const float2*)(po + XS + YS);
                const float g0 = tail ? po[2] : 0.f;
                const float g1 = tail ? po[YS + 2] : 0.f;
                const float g2 = tail ? po[XS + 2] : 0.f;
                const float g3 = tail ? po[XS + YS + 2] : 0.f;
                #pragma unroll
                for (int k = 0; k < 2; k++) {
                    const float zc0 = k ? t0.y : t0.x, zc1 = k ? e0 : t0.y;
                    const float zc2 = k ? t1.y : t1.x, zc3 = k ? e1 : t1.y;
                    const float zc4 = k ? t2.y : t2.x, zc5 = k ? e2 : t2.y;
                    const float zc6 = k ? t3.y : t3.x, zc7 = k ? e3 : t3.y;
                    const float q1 =  C8 * ((zc5 - zc4) + (zc7 - zc6));
                    const float q2 = -C8 * ((zc1 - zc0) + (zc3 - zc2));
                    const float r1 =  C6 * (zc1 - zc5);
                    const float r2 =  C6 * (zc3 - zc7);
                    const float r3 =  C6 * (zc4 - zc0);
                    const float r4 =  C6 * (zc6 - zc2);
                    const float c0 = k ? f0.y : f0.x, c1 = k ? g0 : f0.y;
                    const float c2 = k ? f1.y : f1.x, c3 = k ? g1 : f1.y;
                    const float c4 = k ? f2.y : f2.x, c5 = k ? g2 : f2.y;
                    const float c6 = k ? f3.y : f3.x, c7 = k ? g3 : f3.y;
                    const float nacc =
                          c0 * (q2 + r3) + c1 * (q2 + r1)
                        + c2 * (q2 + r4) + c3 * (q2 + r2)
                        + (c4 + c6) * (q1 + (r3 + r4))
                        + (c5 + c7) * (q1 + (r1 + r2));
                    const float cen = ((c0 + c1) + (c2 + c3)) + ((c4 + c5) + (c6 + c7));
                    if (k == 0) { num0 += nacc; cx0 = cen; }
                    else        { num1 += nacc; cx1 = cen; }
                }
            }
            {   // by batch
                const float* py = po + SPATIAL;
                const float2 f0 = *(const float2*)(py);
                const float2 f1 = *(const float2*)(py + YS);
                const float2 f2 = *(const float2*)(py + XS);
                const float2 f3 = *(const float2*)(py + XS + YS);
                const float g0 = tail ? py[2] : 0.f;
                const float g1 = tail ? py[YS + 2] : 0.f;
                const float g2 = tail ? py[XS + 2] : 0.f;
                const float g3 = tail ? py[XS + YS + 2] : 0.f;
                #pragma unroll
                for (int k = 0; k < 2; k++) {
                    const float zc0 = k ? t0.y : t0.x, zc1 = k ? e0 : t0.y;
                    const float zc2 = k ? t1.y : t1.x, zc3 = k ? e1 : t1.y;
                    const float zc4 = k ? t2.y : t2.x, zc5 = k ? e2 : t2.y;
                    const float zc6 = k ? t3.y : t3.x, zc7 = k ? e3 : t3.y;
                    const float s1 =  C8 * ((zc3 - zc2) + (zc7 - zc6));
                    const float s2 = -C8 * ((zc1 - zc0) + (zc5 - zc4));
                    const float u1 =  C6 * (zc5 - zc7);
                    const float u2 =  C6 * (zc1 - zc3);
                    const float u3 =  C6 * (zc6 - zc4);
                    const float u4 =  C6 * (zc2 - zc0);
                    const float c0 = k ? f0.y : f0.x, c1 = k ? g0 : f0.y;
                    const float c2 = k ? f1.y : f1.x, c3 = k ? g1 : f1.y;
                    const float c4 = k ? f2.y : f2.x, c5 = k ? g2 : f2.y;
                    const float c6 = k ? f3.y : f3.x, c7 = k ? g3 : f3.y;
                    const float nacc =
                          c0 * (s2 + u4) + c1 * (s2 + u2)
                        + c4 * (s2 + u3) + c5 * (s2 + u1)
                        + (c2 + c6) * (s1 + (u3 + u4))
                        + (c3 + c7) * (s1 + (u1 + u2));
                    const float cen = ((c0 + c1) + (c2 + c3)) + ((c4 + c5) + (c6 + c7));
                    if (k == 0) { num0 += nacc; cy0 = cen; }
                    else        { num1 += nacc; cy1 = cen; }
                }
            }
            {   // bz batch
                const float* pb = po + 2 * SPATIAL;
                const float2 f0 = *(const float2*)(pb);
                const float2 f1 = *(const float2*)(pb + YS);
                const float2 f2 = *(const float2*)(pb + XS);
                const float2 f3 = *(const float2*)(pb + XS + YS);
                const float g0 = tail ? pb[2] : 0.f;
                const float g1 = tail ? pb[YS + 2] : 0.f;
                const float g2 = tail ? pb[XS + 2] : 0.f;
                const float g3 = tail ? pb[XS + YS + 2] : 0.f;
                #pragma unroll
                for (int k = 0; k < 2; k++) {
                    const float c0 = k ? f0.y : f0.x, c1 = k ? g0 : f0.y;
                    const float c2 = k ? f1.y : f1.x, c3 = k ? g1 : f1.y;
                    const float c4 = k ? f2.y : f2.x, c5 = k ? g2 : f2.y;
                    const float c6 = k ? f3.y : f3.x, c7 = k ? g3 : f3.y;
                    const float nacc = CZ * (((c1 + c3) + (c5 + c7)) - ((c0 + c2) + (c4 + c6)));
                    const float cen = ((c0 + c1) + (c2 + c3)) + ((c4 + c5) + (c6 + c7));
                    if (k == 0) { num0 += nacc; cz0 = cen; }
                    else        { num1 += nacc; cz1 = cen; }
                }
            }

            {   // cell 0 (always valid here)
                const float bxc = 0.125f * cx0, byc = 0.125f * cy0, bzc = 0.125f * cz0;
                const float den = bxc * bxc + byc * byc + bzc * bzc + EPS;
                sd += num0 * num0 / den;
            }
            if (tail) {   // cell 1 valid only if z+1 < 63
                const float bxc = 0.125f * cx1, byc = 0.125f * cy1, bzc = 0.125f * cz1;
                const float den = bxc * bxc + byc * byc + bzc * bzc + EPS;
                sd += num1 * num1 / den;
            }
        }
    }

    // ---- deterministic block reduction ----
    __shared__ float shb[NT], shp[NT], shd[NT];
    const int tid = threadIdx.x;
    shb[tid] = sb;
    shp[tid] = sp;
    shd[tid] = sd;
    __syncthreads();
    for (int s = NT / 2; s > 0; s >>= 1) {
        if (tid < s) {
            shb[tid] += shb[tid + s];
            shp[tid] += shp[tid + s];
            shd[tid] += shd[tid + s];
        }
        __syncthreads();
    }

    __shared__ bool isLast;
    if (tid == 0) {
        g_pb[blockIdx.x] = shb[0];
        g_pp[blockIdx.x] = shp[0];
        g_pd[blockIdx.x] = shd[0];
        __threadfence();
        isLast = (atomicAdd(&g_cnt, 1u) == NB - 1);
    }
    __syncthreads();

    // ---- last block: final deterministic reduce in double ----
    if (isLast) {
        __threadfence();
        __shared__ double rb[NT], rp[NT], rd[NT];
        double db = 0.0, dp = 0.0, dd = 0.0;
        for (int i = tid; i < NB; i += NT) {
            db += (double)__ldcg(&g_pb[i]);
            dp += (double)__ldcg(&g_pp[i]);
            dd += (double)__ldcg(&g_pd[i]);
        }
        rb[tid] = db; rp[tid] = dp; rd[tid] = dd;
        __syncthreads();
        for (int s = NT / 2; s > 0; s >>= 1) {
            if (tid < s) {
                rb[tid] += rb[tid + s];
                rp[tid] += rp[tid + s];
                rd[tid] += rd[tid + s];
            }
            __syncthreads();
        }
        if (tid == 0) {
            const double N = 8388608.0;            // 2*256*256*64
            const double M = 8193150.0;            // 2*255*255*63
            const double loss_b   = rb[0] / N;
            const double loss_p   = rp[0] / N;
            const double loss_div = rd[0] / M * 1.0e4;   // / DX^2 / DY^2
            out[0] = (float)(1000.0 * loss_b + 1000.0 * loss_p);
            out[1] = (float)(100.0 * loss_div);
            g_cnt = 0;                              // reset for graph replay
        }
    }
}

extern "C" void kernel_launch(void* const* d_in, const int* in_sizes, int n_in,
                              void* d_out, int out_size)
{
    const float* outputs = (const float*)d_in[0];
    const float* targets = (const float*)d_in[1];
    float* out = (float*)d_out;
    loss_kernel<<<NB, NT>>>(outputs, targets, out);
}

// round 11
// speedup vs baseline: 1.1798x; 1.1642x over previous
#include <cuda_runtime.h>

#define NT 256
#define NB 2220                    // 5 blocks/SM x 148 SMs x 3 exact waves
#define SPATIAL (256 * 256 * 64)   // 4194304
#define NTOT    (2 * SPATIAL)      // 8388608
#define XS (256 * 64)              // x stride
#define YS 64                      // y stride

__device__ float g_pb[NB];
__device__ float g_pp[NB];
__device__ float g_pd[NB];
__device__ unsigned int g_cnt = 0;

__global__ __launch_bounds__(NT, 5) void loss_kernel(
    const float* __restrict__ outp, const float* __restrict__ tgt,
    float* __restrict__ out)
{
    const float EPS = 1e-10f;
    const float C8  = 0.0125f;        // 0.125 * DX
    const float C6  = 0.1f / 6.0f;    // DX/6
    const float CZ  = 0.0025f;        // 0.25 * DX * DY

    float sb = 0.f, sp = 0.f, sd = 0.f;

    for (int idx = blockIdx.x * NT + threadIdx.x; idx < NTOT; idx += NB * NT) {
        const int b    = idx >> 22;
        const int sidx = idx & (SPATIAL - 1);
        const int z    = sidx & 63;
        const int y    = (sidx >> 6) & 255;
        const int x    = sidx >> 14;

        const float* po = outp + (size_t)b * 3 * SPATIAL + sidx;   // bx_p
        const float* pt = tgt  + (size_t)b * 4 * SPATIAL + sidx;   // bx_t

        // ---- pointwise losses (fast approximate division) ----
        const float bxp = po[0], byp = po[SPATIAL], bzp = po[2 * SPATIAL];
        {
            const float bxt = pt[0], byt = pt[SPATIAL], bzt = pt[2 * SPATIAL];
            const float bxt2 = bxt * bxt, byt2 = byt * byt, bzt2 = bzt * bzt;
            const float t1 = bxp * bxp + byp * byp - bxt2 - byt2;
            sb += __fdividef(t1 * t1, bxt2 + byt2 + EPS);
            const float dv = bzp - bzt;
            const float dv2 = dv * dv;
            sb += __fdividef(dv2 * dv2, bzt2 + EPS);
            const float cr = bxp * byt - byp * bxt;
            sp += __fdividef(cr * cr, bxt2 + byt2 + bzt2 + EPS);
        }

        // ---- divergence flux loss, coefficient-streamed ----
        if (x < 255 && y < 255 && z < 63) {
            // corner c = (i,j,k) -> i*4 + j*2 + k; offset i*XS + j*YS + k
            const float* pz = pt + 3 * SPATIAL;
            const float z0 = pz[0],       z1 = pz[1];
            const float z2 = pz[YS],      z3 = pz[YS + 1];
            const float z4 = pz[XS],      z5 = pz[XS + 1];
            const float z6 = pz[XS + YS], z7 = pz[XS + YS + 1];

            // bx coefficients
            const float q1 =  C8 * (z5 - z4 + z7 - z6);
            const float q2 = -C8 * (z1 - z0 + z3 - z2);
            const float r1 =  C6 * (z1 - z5);
            const float r2 =  C6 * (z3 - z7);
            const float r3 =  C6 * (z4 - z0);
            const float r4 =  C6 * (z6 - z2);
            // by coefficients
            const float s1 =  C8 * (z3 - z2 + z7 - z6);
            const float s2 = -C8 * (z1 - z0 + z5 - z4);
            const float u1 =  C6 * (z5 - z7);
            const float u2 =  C6 * (z1 - z3);
            const float u3 =  C6 * (z6 - z4);
            const float u4 =  C6 * (z2 - z0);

            float num, bxc, byc, bzc;
            {   // bx batch (c0 reused from pointwise load)
                const float c0 = bxp,         c1 = po[1];
                const float c2 = po[YS],      c3 = po[YS + 1];
                const float c4 = po[XS],      c5 = po[XS + 1];
                const float c6 = po[XS + YS], c7 = po[XS + YS + 1];
                num = c0 * (q2 + r3) + c1 * (q2 + r1)
                    + c2 * (q2 + r4) + c3 * (q2 + r2)
                    + (c4 + c6) * (q1 + (r3 + r4))
                    + (c5 + c7) * (q1 + (r1 + r2));
                bxc = ((c0 + c1) + (c2 + c3)) + ((c4 + c5) + (c6 + c7));
            }
            {   // by batch
                const float* py = po + SPATIAL;
                const float c0 = byp,         c1 = py[1];
                const float c2 = py[YS],      c3 = py[YS + 1];
                const float c4 = py[XS],      c5 = py[XS + 1];
                const float c6 = py[XS + YS], c7 = py[XS + YS + 1];
                num += c0 * (s2 + u4) + c1 * (s2 + u2)
                     + c4 * (s2 + u3) + c5 * (s2 + u1)
                     + (c2 + c6) * (s1 + (u3 + u4))
                     + (c3 + c7) * (s1 + (u1 + u2));
                byc = ((c0 + c1) + (c2 + c3)) + ((c4 + c5) + (c6 + c7));
            }
            {   // bz batch
                const float* pb = po + 2 * SPATIAL;
                const float c0 = bzp,         c1 = pb[1];
                const float c2 = pb[YS],      c3 = pb[YS + 1];
                const float c4 = pb[XS],      c5 = pb[XS + 1];
                const float c6 = pb[XS + YS], c7 = pb[XS + YS + 1];
                num += CZ * (((c1 + c3) + (c5 + c7)) - ((c0 + c2) + (c4 + c6)));
                bzc = ((c0 + c1) + (c2 + c3)) + ((c4 + c5) + (c6 + c7));
            }
            bxc *= 0.125f; byc *= 0.125f; bzc *= 0.125f;
            const float den = bxc * bxc + byc * byc + bzc * bzc + EPS;
            sd += __fdividef(num * num, den);
        }
    }

    // ---- deterministic block reduction ----
    __shared__ float shb[NT], shp[NT], shd[NT];
    const int tid = threadIdx.x;
    shb[tid] = sb;
    shp[tid] = sp;
    shd[tid] = sd;
    __syncthreads();
    for (int s = NT / 2; s > 0; s >>= 1) {
        if (tid < s) {
            shb[tid] += shb[tid + s];
            shp[tid] += shp[tid + s];
            shd[tid] += shd[tid + s];
        }
        __syncthreads();
    }

    __shared__ bool isLast;
    if (tid == 0) {
        g_pb[blockIdx.x] = shb[0];
        g_pp[blockIdx.x] = shp[0];
        g_pd[blockIdx.x] = shd[0];
        __threadfence();
        isLast = (atomicAdd(&g_cnt, 1u) == NB - 1);
    }
    __syncthreads();

    // ---- last block: final deterministic reduce in double ----
    if (isLast) {
        __threadfence();
        __shared__ double rb[NT], rp[NT], rd[NT];
        double db = 0.0, dp = 0.0, dd = 0.0;
        for (int i = tid; i < NB; i += NT) {
            db += (double)__ldcg(&g_pb[i]);
            dp += (double)__ldcg(&g_pp[i]);
            dd += (double)__ldcg(&g_pd[i]);
        }
        rb[tid] = db; rp[tid] = dp; rd[tid] = dd;
        __syncthreads();
        for (int s = NT / 2; s > 0; s >>= 1) {
            if (tid < s) {
                rb[tid] += rb[tid + s];
                rp[tid] += rp[tid + s];
                rd[tid] += rd[tid + s];
            }
            __syncthreads();
        }
        if (tid == 0) {
            const double N = 8388608.0;            // 2*256*256*64
            const double M = 8193150.0;            // 2*255*255*63
            const double loss_b   = rb[0] / N;
            const double loss_p   = rp[0] / N;
            const double loss_div = rd[0] / M * 1.0e4;   // / DX^2 / DY^2
            out[0] = (float)(1000.0 * loss_b + 1000.0 * loss_p);
            out[1] = (float)(100.0 * loss_div);
            g_cnt = 0;                              // reset for graph replay
        }
    }
}

extern "C" void kernel_launch(void* const* d_in, const int* in_sizes, int n_in,
                              void* d_out, int out_size)
{
    const float* outputs = (const float*)d_in[0];
    const float* targets = (const float*)d_in[1];
    float* out = (float*)d_out;
    loss_kernel<<<NB, NT>>>(outputs, targets, out);
}

// round 13
// speedup vs baseline: 1.2259x; 1.0391x over previous
#include <cuda_runtime.h>

#define NT 256
#define NB 2664                    // 6 blocks/SM x 148 SMs x 3 exact waves
#define SPATIAL (256 * 256 * 64)   // 4194304
#define NTOT    (2 * SPATIAL)      // 8388608
#define XS (256 * 64)              // x stride
#define YS 64                      // y stride

__device__ float g_pb[NB];
__device__ float g_pp[NB];
__device__ float g_pd[NB];
__device__ unsigned int g_cnt = 0;

__global__ __launch_bounds__(NT, 6) void loss_kernel(
    const float* __restrict__ outp, const float* __restrict__ tgt,
    float* __restrict__ out)
{
    const float EPS = 1e-10f;
    const float C8  = 0.0125f;        // 0.125 * DX
    const float C6  = 0.1f / 6.0f;    // DX/6
    const float CZ  = 0.0025f;        // 0.25 * DX * DY

    float sb = 0.f, sp = 0.f, sd = 0.f;

    for (int idx = blockIdx.x * NT + threadIdx.x; idx < NTOT; idx += NB * NT) {
        const int b    = idx >> 22;
        const int sidx = idx & (SPATIAL - 1);
        const int z    = sidx & 63;
        const int y    = (sidx >> 6) & 255;
        const int x    = sidx >> 14;

        const float* po = outp + (size_t)b * 3 * SPATIAL + sidx;   // bx_p
        const float* pt = tgt  + (size_t)b * 4 * SPATIAL + sidx;   // bx_t

        // ---- pointwise losses (fast approximate division) ----
        const float bxp = po[0], byp = po[SPATIAL], bzp = po[2 * SPATIAL];
        {
            const float bxt = pt[0], byt = pt[SPATIAL], bzt = pt[2 * SPATIAL];
            const float bxt2 = bxt * bxt, byt2 = byt * byt, bzt2 = bzt * bzt;
            const float t1 = bxp * bxp + byp * byp - bxt2 - byt2;
            sb += __fdividef(t1 * t1, bxt2 + byt2 + EPS);
            const float dv = bzp - bzt;
            const float dv2 = dv * dv;
            sb += __fdividef(dv2 * dv2, bzt2 + EPS);
            const float cr = bxp * byt - byp * bxt;
            sp += __fdividef(cr * cr, bxt2 + byt2 + bzt2 + EPS);
        }

        // ---- divergence flux loss, coefficient-streamed ----
        if (x < 255 && y < 255 && z < 63) {
            // corner c = (i,j,k) -> i*4 + j*2 + k; offset i*XS + j*YS + k
            const float* pz = pt + 3 * SPATIAL;
            const float z0 = pz[0],       z1 = pz[1];
            const float z2 = pz[YS],      z3 = pz[YS + 1];
            const float z4 = pz[XS],      z5 = pz[XS + 1];
            const float z6 = pz[XS + YS], z7 = pz[XS + YS + 1];

            // bx coefficients
            const float q1 =  C8 * (z5 - z4 + z7 - z6);
            const float q2 = -C8 * (z1 - z0 + z3 - z2);
            const float r1 =  C6 * (z1 - z5);
            const float r2 =  C6 * (z3 - z7);
            const float r3 =  C6 * (z4 - z0);
            const float r4 =  C6 * (z6 - z2);
            // by coefficients
            const float s1 =  C8 * (z3 - z2 + z7 - z6);
            const float s2 = -C8 * (z1 - z0 + z5 - z4);
            const float u1 =  C6 * (z5 - z7);
            const float u2 =  C6 * (z1 - z3);
            const float u3 =  C6 * (z6 - z4);
            const float u4 =  C6 * (z2 - z0);

            float num, bxc, byc, bzc;
            {   // bx batch (c0 reused from pointwise load)
                const float c0 = bxp,         c1 = po[1];
                const float c2 = po[YS],      c3 = po[YS + 1];
                const float c4 = po[XS],      c5 = po[XS + 1];
                const float c6 = po[XS + YS], c7 = po[XS + YS + 1];
                num = c0 * (q2 + r3) + c1 * (q2 + r1)
                    + c2 * (q2 + r4) + c3 * (q2 + r2)
                    + (c4 + c6) * (q1 + (r3 + r4))
                    + (c5 + c7) * (q1 + (r1 + r2));
                bxc = ((c0 + c1) + (c2 + c3)) + ((c4 + c5) + (c6 + c7));
            }
            {   // by batch
                const float* py = po + SPATIAL;
                const float c0 = byp,         c1 = py[1];
                const float c2 = py[YS],      c3 = py[YS + 1];
                const float c4 = py[XS],      c5 = py[XS + 1];
                const float c6 = py[XS + YS], c7 = py[XS + YS + 1];
                num += c0 * (s2 + u4) + c1 * (s2 + u2)
                     + c4 * (s2 + u3) + c5 * (s2 + u1)
                     + (c2 + c6) * (s1 + (u3 + u4))
                     + (c3 + c7) * (s1 + (u1 + u2));
                byc = ((c0 + c1) + (c2 + c3)) + ((c4 + c5) + (c6 + c7));
            }
            {   // bz batch
                const float* pb = po + 2 * SPATIAL;
                const float c0 = bzp,         c1 = pb[1];
                const float c2 = pb[YS],      c3 = pb[YS + 1];
                const float c4 = pb[XS],      c5 = pb[XS + 1];
                const float c6 = pb[XS + YS], c7 = pb[XS + YS + 1];
                num += CZ * (((c1 + c3) + (c5 + c7)) - ((c0 + c2) + (c4 + c6)));
                bzc = ((c0 + c1) + (c2 + c3)) + ((c4 + c5) + (c6 + c7));
            }
            bxc *= 0.125f; byc *= 0.125f; bzc *= 0.125f;
            const float den = bxc * bxc + byc * byc + bzc * bzc + EPS;
            sd += __fdividef(num * num, den);
        }
    }

    // ---- deterministic block reduction ----
    __shared__ float shb[NT], shp[NT], shd[NT];
    const int tid = threadIdx.x;
    shb[tid] = sb;
    shp[tid] = sp;
    shd[tid] = sd;
    __syncthreads();
    for (int s = NT / 2; s > 0; s >>= 1) {
        if (tid < s) {
            shb[tid] += shb[tid + s];
            shp[tid] += shp[tid + s];
            shd[tid] += shd[tid + s];
        }
        __syncthreads();
    }

    __shared__ bool isLast;
    if (tid == 0) {
        g_pb[blockIdx.x] = shb[0];
        g_pp[blockIdx.x] = shp[0];
        g_pd[blockIdx.x] = shd[0];
        __threadfence();
        isLast = (atomicAdd(&g_cnt, 1u) == NB - 1);
    }
    __syncthreads();

    // ---- last block: final deterministic reduce in double ----
    if (isLast) {
        __threadfence();
        __shared__ double rb[NT], rp[NT], rd[NT];
        double db = 0.0, dp = 0.0, dd = 0.0;
        for (int i = tid; i < NB; i += NT) {
            db += (double)__ldcg(&g_pb[i]);
            dp += (double)__ldcg(&g_pp[i]);
            dd += (double)__ldcg(&g_pd[i]);
        }
        rb[tid] = db; rp[tid] = dp; rd[tid] = dd;
        __syncthreads();
        for (int s = NT / 2; s > 0; s >>= 1) {
            if (tid < s) {
                rb[tid] += rb[tid + s];
                rp[tid] += rp[tid + s];
                rd[tid] += rd[tid + s];
            }
            __syncthreads();
        }
        if (tid == 0) {
            const double N = 8388608.0;            // 2*256*256*64
            const double M = 8193150.0;            // 2*255*255*63
            const double loss_b   = rb[0] / N;
            const double loss_p   = rp[0] / N;
            const double loss_div = rd[0] / M * 1.0e4;   // / DX^2 / DY^2
            out[0] = (float)(1000.0 * loss_b + 1000.0 * loss_p);
            out[1] = (float)(100.0 * loss_div);
            g_cnt = 0;                              // reset for graph replay
        }
    }
}

extern "C" void kernel_launch(void* const* d_in, const int* in_sizes, int n_in,
                              void* d_out, int out_size)
{
    const float* outputs = (const float*)d_in[0];
    const float* targets = (const float*)d_in[1];
    float* out = (float*)d_out;
    loss_kernel<<<NB, NT>>>(outputs, targets, out);
}